// round 7
// baseline (speedup 1.0000x reference)
#include <cuda_runtime.h>
#include <cuda_bf16.h>

// PointPillars BEV scatter, inverted as a gather, software-pipelined:
//   1) cudaMemsetAsync grid to 0xFF (-1)
//   2) scatter pillar ids into grid[(b*H+y)*W+x]
//   3) persistent gather blocks (3/SM): prefetch idx 2 tiles ahead, features 1
//      tile ahead (branch-free clamped loads => full MLP), transpose through
//      smem, coalesced streaming float4 stores per channel plane.
#define BEV_H 496
#define BEV_W 432
#define BB    4
#define CC    64
#define GRID_CELLS (BB * BEV_H * BEV_W)   // 857088
#define TILE_X 128
#define NT_X   4                           // ceil(432/128)
#define NT     (BB * BEV_H * NT_X)         // 7936 tiles
#define ROW_STRIDE 132
#define GATHER_BLOCKS 456                  // 3 per SM on 152-SM GB300

__device__ int g_grid[GRID_CELLS];

__global__ void scatter_ids_kernel(const int* __restrict__ coords, int M) {
    int m = blockIdx.x * blockDim.x + threadIdx.x;
    if (m < M) {
        int b = coords[3 * m + 0];
        int y = coords[3 * m + 1];
        int x = coords[3 * m + 2];
        g_grid[(b * BEV_H + y) * BEV_W + x] = m;
    }
}

__global__ __launch_bounds__(512, 3) void gather_kernel(
    const float* __restrict__ feat, float* __restrict__ out)
{
    const int tid   = threadIdx.x;
    const int p     = tid & 15;       // gather: channel quad
    const int rbase = tid >> 4;       // gather: cell sub-index (0..31)
    const int s4p   = (p >> 1) << 2;  // smem swizzle key for writes
    const int xq    = tid & 31;       // stage2: x quad
    const int cq    = tid >> 5;       // stage2: channel quad (0..15)

    __shared__ __align__(16) float stile[CC * ROW_STRIDE];  // 33792 B

    const int step = gridDim.x;
    const int t0   = blockIdx.x;

    int    idx_n[4];   // indices for tile t+step
    int    idx_p[4];   // indices for tile t+2*step (in flight)
    float4 v[4];       // features for tile t

    // ---- index prefetch (branch-free; OOB x -> -1) ----
    auto load_idx = [&](int t, int* dst) {
#pragma unroll
        for (int i = 0; i < 4; i++) {
            int r  = t >> 2;                    // combined (b*H + y)
            int tx = (t & 3) * TILE_X;
            int x  = tx + i * 32 + rbase;
            dst[i] = (x < BEV_W) ? __ldg(&g_grid[r * BEV_W + x]) : -1;
        }
    };

    // ---- branch-free gather: always load (clamped row), select zero after ----
    auto gather = [&](const int* idx, float4* dst) {
#pragma unroll
        for (int i = 0; i < 4; i++) {
            int  safe = idx[i] < 0 ? 0 : idx[i];
            float4 w  = __ldg(reinterpret_cast<const float4*>(feat)
                              + (size_t)safe * (CC / 4) + p);
            bool ok = idx[i] >= 0;
            dst[i] = make_float4(ok ? w.x : 0.f, ok ? w.y : 0.f,
                                 ok ? w.z : 0.f, ok ? w.w : 0.f);
        }
    };

    // ---- prologue: fill the pipeline ----
    load_idx(t0, idx_n);
    gather(idx_n, v);                       // features for tile t0
    if (t0 + step < NT) load_idx(t0 + step, idx_n);

    const size_t plane = (size_t)BEV_H * BEV_W;

    for (int t = t0; t < NT; t += step) {
        // Stage 1: store tile t's features into transposed smem (tile-invariant addrs)
#pragma unroll
        for (int i = 0; i < 4; i++) {
            int rl = i * 32 + rbase;
            int rx = rl ^ s4p;
            stile[(4 * p + 0) * ROW_STRIDE + rx] = v[i].x;
            stile[(4 * p + 1) * ROW_STRIDE + rx] = v[i].y;
            stile[(4 * p + 2) * ROW_STRIDE + rx] = v[i].z;
            stile[(4 * p + 3) * ROW_STRIDE + rx] = v[i].w;
        }

        // Prefetch indices for t+2*step; gather features for t+step into v
        // (LDGs stay in flight across the barrier + stage 2 below).
        if (t + 2 * step < NT) load_idx(t + 2 * step, idx_p);
        if (t + step < NT)     gather(idx_n, v);

        __syncthreads();

        // Stage 2: conflict-free LDS.128 over x, coalesced streaming stores.
        {
            int r  = t >> 2;
            int b  = r / BEV_H;
            int y  = r - b * BEV_H;
            int tx = (t & 3) * TILE_X;
            int x0 = tx + 4 * xq;
            if (x0 < BEV_W) {
                size_t base = ((size_t)(b * CC + 4 * cq) * BEV_H + y) * BEV_W + x0;
#pragma unroll
                for (int j = 0; j < 4; j++) {
                    int c  = 4 * cq + j;
                    int s4 = ((c >> 3) & 7) << 2;
                    float4 o = *reinterpret_cast<const float4*>(
                        &stile[c * ROW_STRIDE + ((4 * xq) ^ s4)]);
                    __stcs(reinterpret_cast<float4*>(out + base + (size_t)j * plane), o);
                }
            }
        }

        __syncthreads();   // protect smem before next iteration's STS

        // rotate index pipeline
#pragma unroll
        for (int i = 0; i < 4; i++) idx_n[i] = idx_p[i];
    }
}

extern "C" void kernel_launch(void* const* d_in, const int* in_sizes, int n_in,
                              void* d_out, int out_size)
{
    const int*   coords = (const int*)d_in[0];    // (M, 3) int32 [b, y, x]
    const float* feat   = (const float*)d_in[1];  // (M, 64) float32
    float*       out    = (float*)d_out;          // (4, 64, 496, 432) float32

    const int M = in_sizes[0] / 3;

    void* grid_ptr = nullptr;
    cudaGetSymbolAddress(&grid_ptr, g_grid);
    cudaMemsetAsync(grid_ptr, 0xFF, GRID_CELLS * sizeof(int));  // all cells = -1

    scatter_ids_kernel<<<(M + 255) / 256, 256>>>(coords, M);

    gather_kernel<<<GATHER_BLOCKS, 512>>>(feat, out);
}

// round 9
// speedup vs baseline: 1.2654x; 1.2654x over previous
#include <cuda_runtime.h>
#include <cuda_bf16.h>

// PointPillars BEV scatter, inverted as a gather.
//   1) cudaMemsetAsync grid to 0xFF (-1)
//   2) scatter pillar ids into grid[(b*H+y)*W+x]
//   3) persistent gather blocks (3/SM), double-buffered smem tile, ONE barrier
//      per tile. Index ring prefetched 2 tiles ahead; per-cell branchy feature
//      gather (empty cell -> no load); unconditional STS (zeros for empties);
//      conflict-free LDS.128 + coalesced streaming STG.128 per channel plane.
#define BEV_H 496
#define BEV_W 432
#define BB    4
#define CC    64
#define GRID_CELLS (BB * BEV_H * BEV_W)   // 857088
#define TILE_X 128
#define NT     (BB * BEV_H * 4)           // 7936 tiles (4 x-tiles per row)
#define ROW_STRIDE 132
#define TILE_FLOATS (CC * ROW_STRIDE)     // 8448 floats = 33792 B
#define GATHER_BLOCKS 456                 // 3 per SM on 152-SM GB300
#define SMEM_BYTES (2 * TILE_FLOATS * 4 + 4 * TILE_X * 4)  // 69632 B

__device__ int g_grid[GRID_CELLS];

__global__ void scatter_ids_kernel(const int* __restrict__ coords, int M) {
    int m = blockIdx.x * blockDim.x + threadIdx.x;
    if (m < M) {
        int b = coords[3 * m + 0];
        int y = coords[3 * m + 1];
        int x = coords[3 * m + 2];
        g_grid[(b * BEV_H + y) * BEV_W + x] = m;
    }
}

__global__ __launch_bounds__(512, 3) void gather_kernel(
    const float* __restrict__ feat, float* __restrict__ out)
{
    extern __shared__ __align__(16) float smem[];
    float* vbuf  = smem;                       // [2][TILE_FLOATS]
    int*   sring = (int*)(smem + 2 * TILE_FLOATS);  // [4][TILE_X]

    const int tid   = threadIdx.x;
    const int p     = tid & 15;        // gather: channel quad
    const int rbase = tid >> 4;        // gather: cell sub-index (0..31)
    const int s4p   = (p >> 1) << 2;   // smem swizzle key for writes
    const int xq    = tid & 31;        // stage2: x quad
    const int cq    = tid >> 5;        // stage2: channel quad (0..15)

    const int step = gridDim.x;
    const int t0   = blockIdx.x;
    const size_t plane = (size_t)BEV_H * BEV_W;
    const float4* feat4 = reinterpret_cast<const float4*>(feat);

    // ---- index loader: one warp, per-component bounds guard (x >= W -> -1) ----
    auto load_idx = [&](int t, int slot) {
        if (tid < 32) {
            int r  = t >> 2;
            int tx = (t & 3) * TILE_X;
            int x0 = tx + 4 * tid;
            int base = r * BEV_W;
            int4 v;
            v.x = (x0 + 0 < BEV_W) ? __ldg(&g_grid[base + x0 + 0]) : -1;
            v.y = (x0 + 1 < BEV_W) ? __ldg(&g_grid[base + x0 + 1]) : -1;
            v.z = (x0 + 2 < BEV_W) ? __ldg(&g_grid[base + x0 + 2]) : -1;
            v.w = (x0 + 3 < BEV_W) ? __ldg(&g_grid[base + x0 + 3]) : -1;
            *reinterpret_cast<int4*>(&sring[slot * TILE_X + 4 * tid]) = v;
        }
    };

    // ---- per-cell branchy gather: empty cell -> zero, no load ----
    auto gather = [&](int slot, float4* dst) {
#pragma unroll
        for (int i = 0; i < 4; i++) {
            int idx = sring[slot * TILE_X + i * 32 + rbase];
            float4 w = make_float4(0.f, 0.f, 0.f, 0.f);
            if (idx >= 0) {
                w = __ldg(feat4 + (size_t)idx * (CC / 4) + p);
            }
            dst[i] = w;
        }
    };

    float4 v[4];

    // ---- prologue: idx for first two tiles, gather first tile ----
    load_idx(t0, 0);
    if (t0 + step < NT) load_idx(t0 + step, 1);
    __syncthreads();
    gather(0, v);

    int k = 0;
    for (int t = t0; t < NT; t += step, k++) {
        float* wb = vbuf + (size_t)(k & 1) * TILE_FLOATS;

        // Stage 1: unconditional STS of tile t (zeros for empty cells)
#pragma unroll
        for (int i = 0; i < 4; i++) {
            int rx = (i * 32 + rbase) ^ s4p;
            wb[(4 * p + 0) * ROW_STRIDE + rx] = v[i].x;
            wb[(4 * p + 1) * ROW_STRIDE + rx] = v[i].y;
            wb[(4 * p + 2) * ROW_STRIDE + rx] = v[i].z;
            wb[(4 * p + 3) * ROW_STRIDE + rx] = v[i].w;
        }

        // Prefetch indices 2 tiles ahead; gather features for next tile
        // (these LDGs stay in flight across the barrier + store phase).
        if (t + 2 * step < NT) load_idx(t + 2 * step, (k + 2) & 3);
        if (t + step < NT)     gather((k + 1) & 3, v);

        __syncthreads();

        // Stage 2: conflict-free LDS.128 over x, coalesced streaming stores.
        {
            int r  = t >> 2;
            int b  = r / BEV_H;
            int y  = r - b * BEV_H;
            int x0 = (t & 3) * TILE_X + 4 * xq;
            if (x0 < BEV_W) {
                const float* rb = vbuf + (size_t)(k & 1) * TILE_FLOATS;
                size_t base = ((size_t)(b * CC + 4 * cq) * BEV_H + y) * BEV_W + x0;
#pragma unroll
                for (int j = 0; j < 4; j++) {
                    int c  = 4 * cq + j;
                    int s4 = ((c >> 3) & 7) << 2;
                    float4 o = *reinterpret_cast<const float4*>(
                        &rb[c * ROW_STRIDE + ((4 * xq) ^ s4)]);
                    __stcs(reinterpret_cast<float4*>(out + base + (size_t)j * plane), o);
                }
            }
        }
        // no second barrier: next iteration writes the other vbuf, and the
        // sring slot it writes was last read 3 iterations (3 barriers) ago.
    }
}

extern "C" void kernel_launch(void* const* d_in, const int* in_sizes, int n_in,
                              void* d_out, int out_size)
{
    const int*   coords = (const int*)d_in[0];    // (M, 3) int32 [b, y, x]
    const float* feat   = (const float*)d_in[1];  // (M, 64) float32
    float*       out    = (float*)d_out;          // (4, 64, 496, 432) float32

    const int M = in_sizes[0] / 3;

    void* grid_ptr = nullptr;
    cudaGetSymbolAddress(&grid_ptr, g_grid);
    cudaMemsetAsync(grid_ptr, 0xFF, GRID_CELLS * sizeof(int));  // all cells = -1

    scatter_ids_kernel<<<(M + 255) / 256, 256>>>(coords, M);

    static bool attr_set = false;
    if (!attr_set) {
        cudaFuncSetAttribute(gather_kernel,
                             cudaFuncAttributeMaxDynamicSharedMemorySize,
                             SMEM_BYTES);
        attr_set = true;
    }
    gather_kernel<<<GATHER_BLOCKS, 512, SMEM_BYTES>>>(feat, out);
}

// round 10
// speedup vs baseline: 1.3989x; 1.1055x over previous
#include <cuda_runtime.h>
#include <cuda_bf16.h>

// PointPillars BEV scatter, inverted as a gather.
//   1) cudaMemsetAsync grid to 0xFF (-1)
//   2) scatter pillar ids into grid[(b*H+y)*W+x]
//   3) persistent gather blocks (3/SM), double-buffered smem tile, ONE barrier
//      per tile, 4-slot idx+flag ring prefetched 2 tiles ahead.
//      All-empty 4-cell quads (55%) bypass smem in BOTH directions.
#define BEV_H 496
#define BEV_W 432
#define BB    4
#define CC    64
#define GRID_CELLS (BB * BEV_H * BEV_W)   // 857088
#define TILE_X 128
#define NQ     (TILE_X / 4)               // 32 quads per tile
#define NT     (BB * BEV_H * 4)           // 7936 tiles (4 x-tiles per row)
#define ROW_STRIDE 132
#define TILE_FLOATS (CC * ROW_STRIDE)     // 8448 floats = 33792 B
#define GATHER_BLOCKS 456                 // 3 per SM on 152-SM GB300
// 2 tile buffers + 4-slot idx ring + 4-slot quad-flag ring
#define SMEM_BYTES (2 * TILE_FLOATS * 4 + 4 * TILE_X * 4 + 4 * NQ * 4)

__device__ int g_grid[GRID_CELLS];

__global__ void scatter_ids_kernel(const int* __restrict__ coords, int M) {
    int m = blockIdx.x * blockDim.x + threadIdx.x;
    if (m < M) {
        int b = coords[3 * m + 0];
        int y = coords[3 * m + 1];
        int x = coords[3 * m + 2];
        g_grid[(b * BEV_H + y) * BEV_W + x] = m;
    }
}

__global__ __launch_bounds__(512, 3) void gather_kernel(
    const float* __restrict__ feat, float* __restrict__ out)
{
    extern __shared__ __align__(16) float smem[];
    float* vbuf  = smem;                                   // [2][TILE_FLOATS]
    int*   sring = (int*)(smem + 2 * TILE_FLOATS);         // [4][TILE_X]
    int*   qring = (int*)(smem + 2 * TILE_FLOATS + 4 * TILE_X);  // [4][NQ] 1=empty

    const int tid   = threadIdx.x;
    const int p     = tid & 15;        // gather: channel quad
    const int rbase = tid >> 4;        // gather: cell sub-index (0..31)
    const int s4p   = (p >> 1) << 2;   // smem swizzle key for writes
    const int xq    = tid & 31;        // stage2: x quad
    const int cq    = tid >> 5;        // stage2: channel quad (0..15)

    const int step = gridDim.x;
    const int t0   = blockIdx.x;
    const size_t plane = (size_t)BEV_H * BEV_W;
    const float4* feat4 = reinterpret_cast<const float4*>(feat);

    // ---- index + quad-flag loader: one warp ----
    auto load_idx = [&](int t, int slot) {
        if (tid < 32) {
            int r  = t >> 2;
            int x0 = (t & 3) * TILE_X + 4 * tid;
            int base = r * BEV_W;
            int4 v;
            v.x = (x0 + 0 < BEV_W) ? __ldg(&g_grid[base + x0 + 0]) : -1;
            v.y = (x0 + 1 < BEV_W) ? __ldg(&g_grid[base + x0 + 1]) : -1;
            v.z = (x0 + 2 < BEV_W) ? __ldg(&g_grid[base + x0 + 2]) : -1;
            v.w = (x0 + 3 < BEV_W) ? __ldg(&g_grid[base + x0 + 3]) : -1;
            *reinterpret_cast<int4*>(&sring[slot * TILE_X + 4 * tid]) = v;
            // all four negative <=> AND of sign bits set
            qring[slot * NQ + tid] = ((v.x & v.y & v.z & v.w) < 0) ? 1 : 0;
        }
    };

    // ---- per-cell branchy gather: empty cell -> zero, no load ----
    auto gather = [&](int slot, float4* dst) {
#pragma unroll
        for (int i = 0; i < 4; i++) {
            int idx = sring[slot * TILE_X + i * 32 + rbase];
            float4 w = make_float4(0.f, 0.f, 0.f, 0.f);
            if (idx >= 0) {
                w = __ldg(feat4 + (size_t)idx * (CC / 4) + p);
            }
            dst[i] = w;
        }
    };

    float4 v[4];

    // ---- prologue ----
    load_idx(t0, 0);
    if (t0 + step < NT) load_idx(t0 + step, 1);
    __syncthreads();
    gather(0, v);

    int k = 0;
    for (int t = t0; t < NT; t += step, k++) {
        const int slot = k & 3;
        float* wb = vbuf + (size_t)(k & 1) * TILE_FLOATS;

        // Stage 1: STS only for cells in nonempty quads (zeros for empty cells
        // inside live quads come from the gather's zero registers).
#pragma unroll
        for (int i = 0; i < 4; i++) {
            int rl = i * 32 + rbase;
            if (!qring[slot * NQ + (rl >> 2)]) {
                int rx = rl ^ s4p;
                wb[(4 * p + 0) * ROW_STRIDE + rx] = v[i].x;
                wb[(4 * p + 1) * ROW_STRIDE + rx] = v[i].y;
                wb[(4 * p + 2) * ROW_STRIDE + rx] = v[i].z;
                wb[(4 * p + 3) * ROW_STRIDE + rx] = v[i].w;
            }
        }

        // Prefetch indices 2 tiles ahead; gather features for next tile
        // (LDGs stay in flight across the barrier + store phase).
        if (t + 2 * step < NT) load_idx(t + 2 * step, (k + 2) & 3);
        if (t + step < NT)     gather((k + 1) & 3, v);

        __syncthreads();

        // Stage 2: empty quad -> store zeros directly; else conflict-free
        // LDS.128 then coalesced streaming stores.
        {
            int r  = t >> 2;
            int b  = r / BEV_H;
            int y  = r - b * BEV_H;
            int x0 = (t & 3) * TILE_X + 4 * xq;
            if (x0 < BEV_W) {
                const bool qe = (qring[slot * NQ + xq] != 0);
                const float* rb = vbuf + (size_t)(k & 1) * TILE_FLOATS;
                size_t base = ((size_t)(b * CC + 4 * cq) * BEV_H + y) * BEV_W + x0;
#pragma unroll
                for (int j = 0; j < 4; j++) {
                    float4 o = make_float4(0.f, 0.f, 0.f, 0.f);
                    if (!qe) {
                        int c  = 4 * cq + j;
                        int s4 = ((c >> 3) & 7) << 2;
                        o = *reinterpret_cast<const float4*>(
                            &rb[c * ROW_STRIDE + ((4 * xq) ^ s4)]);
                    }
                    __stcs(reinterpret_cast<float4*>(out + base + (size_t)j * plane), o);
                }
            }
        }
        // Ring safety with one barrier: in window (bar k, bar k+1) readers use
        // slots {k, k+1, k+2} mod 4; the only writer uses slot k+3 mod 4.
    }
}

extern "C" void kernel_launch(void* const* d_in, const int* in_sizes, int n_in,
                              void* d_out, int out_size)
{
    const int*   coords = (const int*)d_in[0];    // (M, 3) int32 [b, y, x]
    const float* feat   = (const float*)d_in[1];  // (M, 64) float32
    float*       out    = (float*)d_out;          // (4, 64, 496, 432) float32

    const int M = in_sizes[0] / 3;

    void* grid_ptr = nullptr;
    cudaGetSymbolAddress(&grid_ptr, g_grid);
    cudaMemsetAsync(grid_ptr, 0xFF, GRID_CELLS * sizeof(int));  // all cells = -1

    scatter_ids_kernel<<<(M + 255) / 256, 256>>>(coords, M);

    static bool attr_set = false;
    if (!attr_set) {
        cudaFuncSetAttribute(gather_kernel,
                             cudaFuncAttributeMaxDynamicSharedMemorySize,
                             SMEM_BYTES);
        attr_set = true;
    }
    gather_kernel<<<GATHER_BLOCKS, 512, SMEM_BYTES>>>(feat, out);
}